// round 3
// baseline (speedup 1.0000x reference)
#include <cuda_runtime.h>
#include <math.h>

#define B 8
#define D 4
#define L 32
#define N 541696          // 736*736
#define NV (N/4)          // 135424 float4 groups
#define DELTA_AGG 0.5f
#define DELTA_DIS 1.5f
#define REG_W 0.001f

// ---- scratch (device globals; no allocation allowed) ----
__device__ float g_cntk[B][L];      // count of pixels with inst_k == l  (l>0 only)
__device__ float g_cnt[B][L];       // count of pixels with inst == l    (l>0 only)
__device__ float g_sumv[B][L];      // sum of agg val per label          (l>0 only)
__device__ float g_sumk[B][L][D];   // sum of emb over inst_k == l       (l>0 only)
__device__ float g_mean[B][L][D];   // kernel-region means

// ---- zero the accumulators (graph replays reuse them) ----
__global__ void k_zero() {
    int i = blockIdx.x * blockDim.x + threadIdx.x;
    if (i < B * L) {
        ((float*)g_cntk)[i] = 0.0f;
        ((float*)g_cnt)[i]  = 0.0f;
        ((float*)g_sumv)[i] = 0.0f;
    }
    if (i < B * L * D) ((float*)g_sumk)[i] = 0.0f;
}

// ---- pass 1: cnt_k, sum_k, cnt ----
__global__ void __launch_bounds__(256) k_pass1(
    const float* __restrict__ emb, const int* __restrict__ inst,
    const float* __restrict__ ker, const float* __restrict__ tmk)
{
    const int b = blockIdx.y;
    __shared__ float s_cntk[L], s_cnt[L];
    __shared__ float s_sumk[L][D];
    for (int i = threadIdx.x; i < L; i += blockDim.x) {
        s_cntk[i] = 0.0f; s_cnt[i] = 0.0f;
        s_sumk[i][0] = 0.0f; s_sumk[i][1] = 0.0f;
        s_sumk[i][2] = 0.0f; s_sumk[i][3] = 0.0f;
    }
    __syncthreads();

    const float4* e0 = (const float4*)(emb + (size_t)b * D * N);
    const float4* e1 = e0 + NV;
    const float4* e2 = e0 + 2 * NV;
    const float4* e3 = e0 + 3 * NV;
    const int4*   ib = (const int4*)(inst + (size_t)b * N);
    const float4* kb = (const float4*)(ker + (size_t)b * N);
    const float4* mb = (const float4*)(tmk + (size_t)b * N);

    int idx    = blockIdx.x * blockDim.x + threadIdx.x;
    int stride = gridDim.x * blockDim.x;

    for (int i = idx; i < NV; i += stride) {
        int4   lv = ib[i];
        float4 kv = kb[i];
        float4 mv = mb[i];
        float4 a  = e0[i];
        float4 c  = e1[i];
        float4 d2 = e2[i];
        float4 f  = e3[i];

#define PIX1(LB, KK, MM, X)                                            \
        if ((MM) > 0.5f) {                                             \
            int li = (LB);                                             \
            if (li != 0) {                                             \
                atomicAdd(&s_cnt[li], 1.0f);                           \
                if ((KK) > 0.5f) {                                     \
                    atomicAdd(&s_cntk[li], 1.0f);                      \
                    atomicAdd(&s_sumk[li][0], a.X);                    \
                    atomicAdd(&s_sumk[li][1], c.X);                    \
                    atomicAdd(&s_sumk[li][2], d2.X);                   \
                    atomicAdd(&s_sumk[li][3], f.X);                    \
                }                                                      \
            }                                                          \
        }
        PIX1(lv.x, kv.x, mv.x, x)
        PIX1(lv.y, kv.y, mv.y, y)
        PIX1(lv.z, kv.z, mv.z, z)
        PIX1(lv.w, kv.w, mv.w, w)
#undef PIX1
    }
    __syncthreads();

    for (int i = threadIdx.x; i < L; i += blockDim.x) {
        if (s_cnt[i] != 0.0f) atomicAdd(&g_cnt[b][i], s_cnt[i]);
        if (s_cntk[i] != 0.0f) {
            atomicAdd(&g_cntk[b][i], s_cntk[i]);
            atomicAdd(&g_sumk[b][i][0], s_sumk[i][0]);
            atomicAdd(&g_sumk[b][i][1], s_sumk[i][1]);
            atomicAdd(&g_sumk[b][i][2], s_sumk[i][2]);
            atomicAdd(&g_sumk[b][i][3], s_sumk[i][3]);
        }
    }
}

// ---- compute emb_mean ----
__global__ void k_mean() {
    int b = blockIdx.x;
    int i = threadIdx.x;         // 128 threads = L*D
    int l = i >> 2, d = i & 3;
    float c = g_cntk[b][l];
    float v = (l == 0) ? 0.0f : g_sumk[b][l][d] / fmaxf(c, 1.0f);
    g_mean[b][l][d] = v;
}

// ---- pass 2: sum_v per label (aggregation loss numerator) ----
__global__ void __launch_bounds__(256) k_pass2(
    const float* __restrict__ emb, const int* __restrict__ inst,
    const float* __restrict__ tmk)
{
    const int b = blockIdx.y;
    __shared__ float4 s_mean[L];
    __shared__ float  s_sumv[L];
    if (threadIdx.x < L) {
        int l = threadIdx.x;
        s_mean[l] = make_float4(g_mean[b][l][0], g_mean[b][l][1],
                                g_mean[b][l][2], g_mean[b][l][3]);
        s_sumv[l] = 0.0f;
    }
    __syncthreads();

    const float4* e0 = (const float4*)(emb + (size_t)b * D * N);
    const float4* e1 = e0 + NV;
    const float4* e2 = e0 + 2 * NV;
    const float4* e3 = e0 + 3 * NV;
    const int4*   ib = (const int4*)(inst + (size_t)b * N);
    const float4* mb = (const float4*)(tmk + (size_t)b * N);

    int idx    = blockIdx.x * blockDim.x + threadIdx.x;
    int stride = gridDim.x * blockDim.x;

    for (int i = idx; i < NV; i += stride) {
        int4   lv = ib[i];
        float4 mv = mb[i];
        float4 a  = e0[i];
        float4 c  = e1[i];
        float4 d2 = e2[i];
        float4 f  = e3[i];

#define PIX2(LB, MM, X)                                                \
        if ((MM) > 0.5f) {                                             \
            int li = (LB);                                             \
            if (li != 0) {                                             \
                float4 mu = s_mean[li];                                \
                float dx = a.X  - mu.x;                                \
                float dy = c.X  - mu.y;                                \
                float dz = d2.X - mu.z;                                \
                float dw = f.X  - mu.w;                                \
                float sq = dx*dx + dy*dy + dz*dz + dw*dw;              \
                float dist = sqrtf(sq);                                \
                float r = fmaxf(dist - DELTA_AGG, 0.0f);               \
                atomicAdd(&s_sumv[li], logf(fmaf(r, r, 1.0f)));        \
            }                                                          \
        }
        PIX2(lv.x, mv.x, x)
        PIX2(lv.y, mv.y, y)
        PIX2(lv.z, mv.z, z)
        PIX2(lv.w, mv.w, w)
#undef PIX2
    }
    __syncthreads();

    for (int i = threadIdx.x; i < L; i += blockDim.x)
        if (s_sumv[i] != 0.0f) atomicAdd(&g_sumv[b][i], s_sumv[i]);
}

// ---- finalize: l_agg + l_dis + l_reg ----
__device__ __forceinline__ float warpsum(float v) {
    #pragma unroll
    for (int o = 16; o > 0; o >>= 1) v += __shfl_xor_sync(0xFFFFFFFFu, v, o);
    return v;
}

__global__ void k_final(float* __restrict__ out) {
    int b = blockIdx.x;
    int l = threadIdx.x;     // 32 threads = L

    float ck  = g_cntk[b][l];
    float tot = warpsum(ck);           // sum over l>0 (g_cntk[b][0] == 0)
    if (l == 0) ck = (float)N - tot;   // pixels with inst_k == 0

    bool present = ck > 0.0f;
    bool nzf     = present && (l > 0);
    unsigned pres_mask = __ballot_sync(0xFFFFFFFFu, present);
    unsigned nz_mask   = __ballot_sync(0xFFFFFFFFu, nzf);
    int num_instance   = __popc(pres_mask);

    float m0 = g_mean[b][l][0];
    float m1 = g_mean[b][l][1];
    float m2 = g_mean[b][l][2];
    float m3 = g_mean[b][l][3];

    // aggregation loss
    float la = nzf ? g_sumv[b][l] / fmaxf(g_cnt[b][l], 1.0f) : 0.0f;
    float l_agg = warpsum(la) / fmaxf((float)(num_instance - 1), 1.0f);

    // discrimination loss: all distinct nz pairs via shuffles
    float dsum = 0.0f;
    int   npl  = 0;
    #pragma unroll
    for (int m = 0; m < 32; m++) {
        float om0 = __shfl_sync(0xFFFFFFFFu, m0, m);
        float om1 = __shfl_sync(0xFFFFFFFFu, m1, m);
        float om2 = __shfl_sync(0xFFFFFFFFu, m2, m);
        float om3 = __shfl_sync(0xFFFFFFFFu, m3, m);
        if (nzf && ((nz_mask >> m) & 1u) && m != l) {
            float dx = m0 - om0, dy = m1 - om1, dz = m2 - om2, dw = m3 - om3;
            float sq = dx*dx + dy*dy + dz*dz + dw*dw;
            float dist = sqrtf(sq);
            float r = fmaxf(2.0f * DELTA_DIS - dist, 0.0f);
            dsum += logf(fmaf(r, r, 1.0f));
            npl++;
        }
    }
    float n_pairs = warpsum((float)npl);
    float l_dis = warpsum(dsum) / fmaxf(n_pairs, 1.0f);
    l_dis = (num_instance > 2) ? l_dis : 0.0f;

    // regularizer (l==0 mean is zero -> contributes 0 but counts in denom)
    float msq = m0*m0 + m1*m1 + m2*m2 + m3*m3;
    float rg  = present ? logf(sqrtf(msq) + 1.0f) : 0.0f;
    float l_reg = warpsum(rg) / fmaxf((float)num_instance, 1.0f) * REG_W;

    if (l == 0) {
        float loss = l_agg + l_dis + l_reg;
        out[b] = (num_instance <= 1) ? 0.0f : loss;
    }
}

extern "C" void kernel_launch(void* const* d_in, const int* in_sizes, int n_in,
                              void* d_out, int out_size) {
    const float* emb  = (const float*)d_in[0];
    const int*   inst = (const int*)d_in[1];
    const float* ker  = (const float*)d_in[2];
    const float* tmk  = (const float*)d_in[3];
    float* out = (float*)d_out;

    k_zero<<<1, 1024>>>();
    dim3 grid(120, B);
    k_pass1<<<grid, 256>>>(emb, inst, ker, tmk);
    k_mean<<<B, L * D>>>();
    k_pass2<<<grid, 256>>>(emb, inst, tmk);
    k_final<<<B, L>>>(out);
}

// round 6
// speedup vs baseline: 1.3078x; 1.3078x over previous
#include <cuda_runtime.h>
#include <math.h>

#define B 8
#define D 4
#define L 32
#define N 541696          // 736*736
#define NV (N/4)          // 135424 float4 groups
#define NW 8              // warps per block (256 threads)
#define DELTA_AGG 0.5f
#define DELTA_DIS 1.5f
#define REG_W 0.001f

// ---- scratch (device globals; no allocation allowed) ----
__device__ float g_cntk[B][L];
__device__ float g_cnt[B][L];
__device__ float g_sumv[B][L];
__device__ float g_sumk[B][L][D];
__device__ float g_mean[B][L][D];

__device__ __forceinline__ float fast_sqrt(float x) {
    float r; asm("sqrt.approx.f32 %0, %1;" : "=f"(r) : "f"(x)); return r;
}

// ---- zero the accumulators (graph replays reuse them) ----
__global__ void k_zero() {
    int i = blockIdx.x * blockDim.x + threadIdx.x;
    if (i < B * L) {
        ((float*)g_cntk)[i] = 0.0f;
        ((float*)g_cnt)[i]  = 0.0f;
        ((float*)g_sumv)[i] = 0.0f;
    }
    if (i < B * L * D) ((float*)g_sumk)[i] = 0.0f;
}

// ---- pass 1: cnt_k, sum_k, cnt (per-warp privatized shared accumulators) ----
// fields: 0=cnt, 1=cntk, 2..5=sumk[d]
__global__ void __launch_bounds__(256) k_pass1(
    const float* __restrict__ emb, const int* __restrict__ inst,
    const float* __restrict__ ker, const float* __restrict__ tmk)
{
    const int b = blockIdx.y;
    __shared__ float sp[NW][6][L];

    for (int i = threadIdx.x; i < NW * 6 * L; i += blockDim.x)
        ((float*)sp)[i] = 0.0f;
    __syncthreads();

    const int wid = threadIdx.x >> 5;
    float (*my)[L] = sp[wid];

    const float4* e0 = (const float4*)(emb + (size_t)b * D * N);
    const float4* e1 = e0 + NV;
    const float4* e2 = e0 + 2 * NV;
    const float4* e3 = e0 + 3 * NV;
    const int4*   ib = (const int4*)(inst + (size_t)b * N);
    const float4* kb = (const float4*)(ker + (size_t)b * N);
    const float4* mb = (const float4*)(tmk + (size_t)b * N);

    int idx    = blockIdx.x * blockDim.x + threadIdx.x;
    int stride = gridDim.x * blockDim.x;

    for (int i = idx; i < NV; i += stride) {
        int4   lv = ib[i];
        float4 kv = kb[i];
        float4 mv = mb[i];
        float4 a  = e0[i];
        float4 c  = e1[i];
        float4 d2 = e2[i];
        float4 f  = e3[i];

#define PIX1(LB, KK, MM, X)                                            \
        {                                                              \
            int li = (LB);                                             \
            if ((MM) > 0.5f && li != 0) {                              \
                atomicAdd(&my[0][li], 1.0f);                           \
                if ((KK) > 0.5f) {                                     \
                    atomicAdd(&my[1][li], 1.0f);                       \
                    atomicAdd(&my[2][li], a.X);                        \
                    atomicAdd(&my[3][li], c.X);                        \
                    atomicAdd(&my[4][li], d2.X);                       \
                    atomicAdd(&my[5][li], f.X);                        \
                }                                                      \
            }                                                          \
        }
        PIX1(lv.x, kv.x, mv.x, x)
        PIX1(lv.y, kv.y, mv.y, y)
        PIX1(lv.z, kv.z, mv.z, z)
        PIX1(lv.w, kv.w, mv.w, w)
#undef PIX1
    }
    __syncthreads();

    // cross-warp reduce then single global atomic per (field,label)
    if (threadIdx.x < 6 * L) {
        int fl = threadIdx.x;
        int fld = fl >> 5, l = fl & 31;
        float s = 0.0f;
        #pragma unroll
        for (int w = 0; w < NW; w++) s += sp[w][fld][l];
        if (s != 0.0f) {
            if      (fld == 0) atomicAdd(&g_cnt[b][l], s);
            else if (fld == 1) atomicAdd(&g_cntk[b][l], s);
            else               atomicAdd(&g_sumk[b][l][fld - 2], s);
        }
    }
}

// ---- compute emb_mean ----
__global__ void k_mean() {
    int b = blockIdx.x;
    int i = threadIdx.x;         // 128 threads = L*D
    int l = i >> 2, d = i & 3;
    float c = g_cntk[b][l];
    float v = (l == 0) ? 0.0f : g_sumk[b][l][d] / fmaxf(c, 1.0f);
    g_mean[b][l][d] = v;
}

// ---- pass 2: sum_v per label. Reverse traversal for L2 reuse. ----
__global__ void __launch_bounds__(256) k_pass2(
    const float* __restrict__ emb, const int* __restrict__ inst,
    const float* __restrict__ tmk)
{
    const int b = blockIdx.y;
    __shared__ float4 s_mean[L];
    __shared__ float  sv[NW][L];

    if (threadIdx.x < L) {
        int l = threadIdx.x;
        s_mean[l] = make_float4(g_mean[b][l][0], g_mean[b][l][1],
                                g_mean[b][l][2], g_mean[b][l][3]);
    }
    for (int i = threadIdx.x; i < NW * L; i += blockDim.x)
        ((float*)sv)[i] = 0.0f;
    __syncthreads();

    const int wid = threadIdx.x >> 5;
    float* my = sv[wid];

    const float4* e0 = (const float4*)(emb + (size_t)b * D * N);
    const float4* e1 = e0 + NV;
    const float4* e2 = e0 + 2 * NV;
    const float4* e3 = e0 + 3 * NV;
    const int4*   ib = (const int4*)(inst + (size_t)b * N);
    const float4* mb = (const float4*)(tmk + (size_t)b * N);

    int idx    = blockIdx.x * blockDim.x + threadIdx.x;
    int stride = gridDim.x * blockDim.x;

    // reverse order: pass1 just streamed this data; the tail of it is still in L2
    for (int i = NV - 1 - idx; i >= 0; i -= stride) {
        int4   lv = ib[i];
        float4 mv = mb[i];
        float4 a  = e0[i];
        float4 c  = e1[i];
        float4 d2 = e2[i];
        float4 f  = e3[i];

#define PIX2(LB, MM, X)                                                \
        {                                                              \
            int li = (LB);                                             \
            if ((MM) > 0.5f && li != 0) {                              \
                float4 mu = s_mean[li];                                \
                float dx = a.X  - mu.x;                                \
                float dy = c.X  - mu.y;                                \
                float dz = d2.X - mu.z;                                \
                float dw = f.X  - mu.w;                                \
                float sq = fmaf(dx, dx, fmaf(dy, dy,                   \
                            fmaf(dz, dz, dw * dw)));                   \
                float r = fmaxf(fast_sqrt(sq) - DELTA_AGG, 0.0f);      \
                atomicAdd(&my[li], __logf(fmaf(r, r, 1.0f)));          \
            }                                                          \
        }
        PIX2(lv.x, mv.x, x)
        PIX2(lv.y, mv.y, y)
        PIX2(lv.z, mv.z, z)
        PIX2(lv.w, mv.w, w)
#undef PIX2
    }
    __syncthreads();

    if (threadIdx.x < L) {
        int l = threadIdx.x;
        float s = 0.0f;
        #pragma unroll
        for (int w = 0; w < NW; w++) s += sv[w][l];
        if (s != 0.0f) atomicAdd(&g_sumv[b][l], s);
    }
}

// ---- finalize: l_agg + l_dis + l_reg ----
__device__ __forceinline__ float warpsum(float v) {
    #pragma unroll
    for (int o = 16; o > 0; o >>= 1) v += __shfl_xor_sync(0xFFFFFFFFu, v, o);
    return v;
}

__global__ void k_final(float* __restrict__ out) {
    int b = blockIdx.x;
    int l = threadIdx.x;     // 32 threads = L

    float ck  = g_cntk[b][l];
    float tot = warpsum(ck);           // sum over l>0 (g_cntk[b][0] == 0)
    if (l == 0) ck = (float)N - tot;   // pixels with inst_k == 0

    bool present = ck > 0.0f;
    bool nzf     = present && (l > 0);
    unsigned pres_mask = __ballot_sync(0xFFFFFFFFu, present);
    unsigned nz_mask   = __ballot_sync(0xFFFFFFFFu, nzf);
    int num_instance   = __popc(pres_mask);

    float m0 = g_mean[b][l][0];
    float m1 = g_mean[b][l][1];
    float m2 = g_mean[b][l][2];
    float m3 = g_mean[b][l][3];

    // aggregation loss
    float la = nzf ? g_sumv[b][l] / fmaxf(g_cnt[b][l], 1.0f) : 0.0f;
    float l_agg = warpsum(la) / fmaxf((float)(num_instance - 1), 1.0f);

    // discrimination loss: all distinct nz pairs via shuffles
    float dsum = 0.0f;
    int   npl  = 0;
    #pragma unroll
    for (int m = 0; m < 32; m++) {
        float om0 = __shfl_sync(0xFFFFFFFFu, m0, m);
        float om1 = __shfl_sync(0xFFFFFFFFu, m1, m);
        float om2 = __shfl_sync(0xFFFFFFFFu, m2, m);
        float om3 = __shfl_sync(0xFFFFFFFFu, m3, m);
        if (nzf && ((nz_mask >> m) & 1u) && m != l) {
            float dx = m0 - om0, dy = m1 - om1, dz = m2 - om2, dw = m3 - om3;
            float sq = dx*dx + dy*dy + dz*dz + dw*dw;
            float dist = sqrtf(sq);
            float r = fmaxf(2.0f * DELTA_DIS - dist, 0.0f);
            dsum += logf(fmaf(r, r, 1.0f));
            npl++;
        }
    }
    float n_pairs = warpsum((float)npl);
    float l_dis = warpsum(dsum) / fmaxf(n_pairs, 1.0f);
    l_dis = (num_instance > 2) ? l_dis : 0.0f;

    // regularizer (l==0 mean is zero -> contributes 0 but counts in denom)
    float msq = m0*m0 + m1*m1 + m2*m2 + m3*m3;
    float rg  = present ? logf(sqrtf(msq) + 1.0f) : 0.0f;
    float l_reg = warpsum(rg) / fmaxf((float)num_instance, 1.0f) * REG_W;

    if (l == 0) {
        float loss = l_agg + l_dis + l_reg;
        out[b] = (num_instance <= 1) ? 0.0f : loss;
    }
}

extern "C" void kernel_launch(void* const* d_in, const int* in_sizes, int n_in,
                              void* d_out, int out_size) {
    const float* emb  = (const float*)d_in[0];
    const int*   inst = (const int*)d_in[1];
    const float* ker  = (const float*)d_in[2];
    const float* tmk  = (const float*)d_in[3];
    float* out = (float*)d_out;

    k_zero<<<1, 1024>>>();
    dim3 grid(111, B);            // 888 blocks = 6 per SM, single wave
    k_pass1<<<grid, 256>>>(emb, inst, ker, tmk);
    k_mean<<<B, L * D>>>();
    k_pass2<<<grid, 256>>>(emb, inst, tmk);
    k_final<<<B, L>>>(out);
}

// round 8
// speedup vs baseline: 1.3478x; 1.0306x over previous
#include <cuda_runtime.h>
#include <math.h>

#define B 8
#define D 4
#define L 32
#define N 541696          // 736*736
#define NV (N/4)          // 135424 float4 groups
#define NW 8              // warps per block (256 threads)
#define DELTA_AGG 0.5f
#define DELTA_DIS 1.5f
#define REG_W 0.001f

// ---- scratch (device globals; zero-initialized at module load, and k_final
//      re-zeroes the accumulators after use so graph replays stay correct) ----
__device__ float g_cntk[B][L];
__device__ float g_cnt[B][L];
__device__ float g_sumv[B][L];
__device__ float g_sumk[B][L][D];
__device__ unsigned char g_lab8[B][N];   // masked labels for pass2 (overwritten fully each run)

__device__ __forceinline__ float fast_sqrt(float x) {
    float r; asm("sqrt.approx.f32 %0, %1;" : "=f"(r) : "f"(x)); return r;
}

// ---- pass 1: cnt_k, sum_k, cnt + emit compacted masked-label map ----
__global__ void __launch_bounds__(256) k_pass1(
    const float* __restrict__ emb, const int* __restrict__ inst,
    const float* __restrict__ ker, const float* __restrict__ tmk)
{
    const int b = blockIdx.y;
    __shared__ float sp[NW][6][L];   // 0=cnt, 1=cntk, 2..5=sumk[d]

    for (int i = threadIdx.x; i < NW * 6 * L; i += blockDim.x)
        ((float*)sp)[i] = 0.0f;
    __syncthreads();

    const int wid = threadIdx.x >> 5;
    float (*my)[L] = sp[wid];

    const float4* e0 = (const float4*)(emb + (size_t)b * D * N);
    const float4* e1 = e0 + NV;
    const float4* e2 = e0 + 2 * NV;
    const float4* e3 = e0 + 3 * NV;
    const int4*   ib = (const int4*)(inst + (size_t)b * N);
    const float4* kb = (const float4*)(ker + (size_t)b * N);
    const float4* mb = (const float4*)(tmk + (size_t)b * N);
    uchar4*       lb = (uchar4*)(g_lab8[b]);

    int idx    = blockIdx.x * blockDim.x + threadIdx.x;
    int stride = gridDim.x * blockDim.x;

    for (int i = idx; i < NV; i += stride) {
        int4   lv = ib[i];
        float4 kv = kb[i];
        float4 mv = mb[i];
        float4 a  = e0[i];
        float4 c  = e1[i];
        float4 d2 = e2[i];
        float4 f  = e3[i];

        uchar4 lo;
        lo.x = (mv.x > 0.5f) ? (unsigned char)lv.x : 0;
        lo.y = (mv.y > 0.5f) ? (unsigned char)lv.y : 0;
        lo.z = (mv.z > 0.5f) ? (unsigned char)lv.z : 0;
        lo.w = (mv.w > 0.5f) ? (unsigned char)lv.w : 0;
        lb[i] = lo;

#define PIX1(LI, KK, X)                                                \
        {                                                              \
            int li = (LI);                                             \
            if (li != 0) {                                             \
                atomicAdd(&my[0][li], 1.0f);                           \
                if ((KK) > 0.5f) {                                     \
                    atomicAdd(&my[1][li], 1.0f);                       \
                    atomicAdd(&my[2][li], a.X);                        \
                    atomicAdd(&my[3][li], c.X);                        \
                    atomicAdd(&my[4][li], d2.X);                       \
                    atomicAdd(&my[5][li], f.X);                        \
                }                                                      \
            }                                                          \
        }
        PIX1(lo.x, kv.x, x)
        PIX1(lo.y, kv.y, y)
        PIX1(lo.z, kv.z, z)
        PIX1(lo.w, kv.w, w)
#undef PIX1
    }
    __syncthreads();

    if (threadIdx.x < 6 * L) {
        int fl = threadIdx.x;
        int fld = fl >> 5, l = fl & 31;
        float s = 0.0f;
        #pragma unroll
        for (int w = 0; w < NW; w++) s += sp[w][fld][l];
        if (s != 0.0f) {
            if      (fld == 0) atomicAdd(&g_cnt[b][l], s);
            else if (fld == 1) atomicAdd(&g_cntk[b][l], s);
            else               atomicAdd(&g_sumk[b][l][fld - 2], s);
        }
    }
}

// ---- pass 2: sum_v per label. Means computed in-block; reverse traversal. ----
__global__ void __launch_bounds__(256, 8) k_pass2(
    const float* __restrict__ emb)
{
    const int b = blockIdx.y;
    __shared__ float4 s_mean[L];
    __shared__ float  sv[NW][L];

    if (threadIdx.x < L * D) {                 // compute emb_mean locally
        int l = threadIdx.x >> 2, d = threadIdx.x & 3;
        float c = g_cntk[b][l];
        float v = (l == 0) ? 0.0f : g_sumk[b][l][d] / fmaxf(c, 1.0f);
        ((float*)s_mean)[threadIdx.x] = v;
    }
    for (int i = threadIdx.x; i < NW * L; i += blockDim.x)
        ((float*)sv)[i] = 0.0f;
    __syncthreads();

    const int wid = threadIdx.x >> 5;
    float* my = sv[wid];

    const float4* e0 = (const float4*)(emb + (size_t)b * D * N);
    const float4* e1 = e0 + NV;
    const float4* e2 = e0 + 2 * NV;
    const float4* e3 = e0 + 3 * NV;
    const uchar4* lb = (const uchar4*)(g_lab8[b]);

    int idx    = blockIdx.x * blockDim.x + threadIdx.x;
    int stride = gridDim.x * blockDim.x;

    // reverse order: pass1 just streamed this data; tail of it is still in L2
    for (int i = NV - 1 - idx; i >= 0; i -= stride) {
        uchar4 lv = lb[i];
        float4 a  = e0[i];
        float4 c  = e1[i];
        float4 d2 = e2[i];
        float4 f  = e3[i];

#define PIX2(LI, X)                                                    \
        {                                                              \
            int li = (LI);                                             \
            if (li != 0) {                                             \
                float4 mu = s_mean[li];                                \
                float dx = a.X  - mu.x;                                \
                float dy = c.X  - mu.y;                                \
                float dz = d2.X - mu.z;                                \
                float dw = f.X  - mu.w;                                \
                float sq = fmaf(dx, dx, fmaf(dy, dy,                   \
                            fmaf(dz, dz, dw * dw)));                   \
                float r = fmaxf(fast_sqrt(sq) - DELTA_AGG, 0.0f);      \
                atomicAdd(&my[li], __logf(fmaf(r, r, 1.0f)));          \
            }                                                          \
        }
        PIX2(lv.x, x)
        PIX2(lv.y, y)
        PIX2(lv.z, z)
        PIX2(lv.w, w)
#undef PIX2
    }
    __syncthreads();

    if (threadIdx.x < L) {
        int l = threadIdx.x;
        float s = 0.0f;
        #pragma unroll
        for (int w = 0; w < NW; w++) s += sv[w][l];
        if (s != 0.0f) atomicAdd(&g_sumv[b][l], s);
    }
}

// ---- finalize: l_agg + l_dis + l_reg; then re-zero accumulators ----
__device__ __forceinline__ float warpsum(float v) {
    #pragma unroll
    for (int o = 16; o > 0; o >>= 1) v += __shfl_xor_sync(0xFFFFFFFFu, v, o);
    return v;
}

__global__ void k_final(float* __restrict__ out) {
    int b = blockIdx.x;
    int l = threadIdx.x;     // 32 threads = L

    float ckraw = g_cntk[b][l];
    float cn    = g_cnt[b][l];
    float sv    = g_sumv[b][l];
    float cdiv  = fmaxf(ckraw, 1.0f);
    float m0 = (l == 0) ? 0.0f : g_sumk[b][l][0] / cdiv;
    float m1 = (l == 0) ? 0.0f : g_sumk[b][l][1] / cdiv;
    float m2 = (l == 0) ? 0.0f : g_sumk[b][l][2] / cdiv;
    float m3 = (l == 0) ? 0.0f : g_sumk[b][l][3] / cdiv;

    float ck  = ckraw;
    float tot = warpsum(ck);           // sum over l>0 (g_cntk[b][0] == 0)
    if (l == 0) ck = (float)N - tot;   // pixels with inst_k == 0

    bool present = ck > 0.0f;
    bool nzf     = present && (l > 0);
    unsigned pres_mask = __ballot_sync(0xFFFFFFFFu, present);
    unsigned nz_mask   = __ballot_sync(0xFFFFFFFFu, nzf);
    int num_instance   = __popc(pres_mask);

    // aggregation loss
    float la = nzf ? sv / fmaxf(cn, 1.0f) : 0.0f;
    float l_agg = warpsum(la) / fmaxf((float)(num_instance - 1), 1.0f);

    // discrimination loss: all distinct nz pairs via shuffles
    float dsum = 0.0f;
    int   npl  = 0;
    #pragma unroll
    for (int m = 0; m < 32; m++) {
        float om0 = __shfl_sync(0xFFFFFFFFu, m0, m);
        float om1 = __shfl_sync(0xFFFFFFFFu, m1, m);
        float om2 = __shfl_sync(0xFFFFFFFFu, m2, m);
        float om3 = __shfl_sync(0xFFFFFFFFu, m3, m);
        if (nzf && ((nz_mask >> m) & 1u) && m != l) {
            float dx = m0 - om0, dy = m1 - om1, dz = m2 - om2, dw = m3 - om3;
            float sq = dx*dx + dy*dy + dz*dz + dw*dw;
            float dist = sqrtf(sq);
            float r = fmaxf(2.0f * DELTA_DIS - dist, 0.0f);
            dsum += logf(fmaf(r, r, 1.0f));
            npl++;
        }
    }
    float n_pairs = warpsum((float)npl);
    float l_dis = warpsum(dsum) / fmaxf(n_pairs, 1.0f);
    l_dis = (num_instance > 2) ? l_dis : 0.0f;

    // regularizer (l==0 mean is zero -> contributes 0 but counts in denom)
    float msq = m0*m0 + m1*m1 + m2*m2 + m3*m3;
    float rg  = present ? logf(sqrtf(msq) + 1.0f) : 0.0f;
    float l_reg = warpsum(rg) / fmaxf((float)num_instance, 1.0f) * REG_W;

    if (l == 0) {
        float loss = l_agg + l_dis + l_reg;
        out[b] = (num_instance <= 1) ? 0.0f : loss;
    }

    // re-zero accumulators for the next graph replay
    g_cntk[b][l] = 0.0f;
    g_cnt[b][l]  = 0.0f;
    g_sumv[b][l] = 0.0f;
    g_sumk[b][l][0] = 0.0f;
    g_sumk[b][l][1] = 0.0f;
    g_sumk[b][l][2] = 0.0f;
    g_sumk[b][l][3] = 0.0f;
}

extern "C" void kernel_launch(void* const* d_in, const int* in_sizes, int n_in,
                              void* d_out, int out_size) {
    const float* emb  = (const float*)d_in[0];
    const int*   inst = (const int*)d_in[1];
    const float* ker  = (const float*)d_in[2];
    const float* tmk  = (const float*)d_in[3];
    float* out = (float*)d_out;

    dim3 grid1(111, B);           // 888 blocks = 6/SM at 40 regs, single wave
    k_pass1<<<grid1, 256>>>(emb, inst, ker, tmk);
    dim3 grid2(148, B);           // 1184 blocks = 8/SM at 32 regs, single wave
    k_pass2<<<grid2, 256>>>(emb);
    k_final<<<B, L>>>(out);
}